// round 15
// baseline (speedup 1.0000x reference)
#include <cuda_runtime.h>
#include <cstdint>

// Problem constants
#define NM      31
#define NPLANE  (NM*NM)        // 961
#define NK      (NM*NM*NM)     // 29791
#define NB      8
#define NPTS    3000
#define NCH     4
#define NBW     12
#define NXH     16             // half-space planes nx = 0..15
#define NSPLIT  4
#define JCHUNK  (NPTS/NSPLIT)  // 750
#define PCHUNK  32             // particles per pipeline stage
#define NCHUNK  ((JCHUNK + PCHUNK - 1)/PCHUNK)   // 24
#define GP      12             // gather particles per CTA (3000 = 250*12)
#define TWO_PI_L 0.628318530717958647692f
#define HALF_L   5.0f
#define INV2V    (1.0f/2000.0f)

typedef unsigned long long u64;

// Packed-F tensors: index q = ((b*NXH+ixh)*32 + iy)*32 + z  (zero-padded)
//   g_FA[q] = { (F_c0.x, F_c1.x), (F_c0.y, F_c1.y) }  (mult+weight folded)
//   g_FB[q] = same for channels 2,3
#define FQN     (NB*NXH*32*32)         // 131072

// Scratch (static device globals; allocation-free per harness rules)
__device__ __align__(256) float2 g_Exy[NB*NPTS*NXH*32];  // [pidx][ixh][i], 98.3 MB
__device__ __align__(256) float2 g_Ez2[NB*NPTS*32];      // [pidx][i], 6.1 MB
__device__ __align__(256) float2 g_E3[NB*NPTS*3*32];     // [pidx][dim][i], 18.4 MB
__device__ float2 g_Fp[NSPLIT*NB*NCH*NXH*NPLANE];        // partial structure factors
__device__ __align__(256) ulonglong2 g_FA[FQN];          // 2 MB
__device__ __align__(256) ulonglong2 g_FB[FQN];          // 2 MB
__device__ float  g_mult[NK];
__device__ float  g_diag;

__device__ __forceinline__ float2 cmul(float2 a, float2 b) {
    return make_float2(a.x*b.x - a.y*b.y, a.x*b.y + a.y*b.x);
}
__device__ __forceinline__ u64 pk(float x, float y) {
    u64 r; asm("mov.b64 %0,{%1,%2};" : "=l"(r) : "f"(x), "f"(y)); return r;
}
__device__ __forceinline__ float2 upk(u64 v) {
    float2 f; asm("mov.b64 {%0,%1},%2;" : "=f"(f.x), "=f"(f.y) : "l"(v)); return f;
}
__device__ __forceinline__ u64 ffma2(u64 a, u64 b, u64 c) {
    u64 d; asm("fma.rn.f32x2 %0,%1,%2,%3;" : "=l"(d) : "l"(a), "l"(b), "l"(c)); return d;
}
__device__ __forceinline__ u64 fmul2(u64 a, u64 b) {
    u64 d; asm("mul.rn.f32x2 %0,%1,%2;" : "=l"(d) : "l"(a), "l"(b)); return d;
}
__device__ __forceinline__ uint32_t smem_u32(const void* p) {
    return static_cast<uint32_t>(__cvta_generic_to_shared(p));
}
__device__ __forceinline__ void cp16(uint32_t dst, const void* src, int srcsz) {
    asm volatile("cp.async.cg.shared.global [%0],[%1],16,%2;"
                 :: "r"(dst), "l"(src), "r"(srcsz));
}
__device__ __forceinline__ void cp_commit() {
    asm volatile("cp.async.commit_group;");
}
template<int N> __device__ __forceinline__ void cp_wait() {
    asm volatile("cp.async.wait_group %0;" :: "n"(N));
}

// ---------------------------------------------------------------------------
// 1) mult(k)
// ---------------------------------------------------------------------------
__global__ void mult_kernel(const float* __restrict__ shift,
                            const float* __restrict__ amp) {
    int i = blockIdx.x * blockDim.x + threadIdx.x;
    if (i >= NK) return;
    int ix = i / NPLANE;
    int r  = i - ix * NPLANE;
    int iy = r / NM;
    int iz = r - iy * NM;
    float kx = TWO_PI_L * (float)(ix - 15);
    float ky = TWO_PI_L * (float)(iy - 15);
    float kz = TWO_PI_L * (float)(iz - 15);
    float k2 = kx*kx + ky*ky + kz*kz;
    float m = 0.0f;
#pragma unroll
    for (int b = 0; b < NBW; b++) {
        m += amp[b] * __expf(-k2 * __expf(2.0f * shift[b]));
    }
    if (k2 == 0.0f) m = 0.0f;
    g_mult[i] = m;
}

// ---------------------------------------------------------------------------
// 2) diag_sum
// ---------------------------------------------------------------------------
__global__ void diag_kernel() {
    __shared__ float sh[1024];
    int tid = threadIdx.x;
    float s = 0.0f;
    for (int i = tid; i < NK; i += 1024) s += g_mult[i];
    sh[tid] = s;
    __syncthreads();
    for (int o = 512; o > 0; o >>= 1) {
        if (tid < o) sh[tid] += sh[tid + o];
        __syncthreads();
    }
    if (tid == 0) g_diag = sh[0] * INV2V;
}

// ---------------------------------------------------------------------------
// 3) E tables: one warp per particle, coalesced 256B row stores.
//    Emits: g_Exy (scatter), g_Ez2 (scatter), g_E3 (gather ex/ey/ez).
// ---------------------------------------------------------------------------
__global__ void etab_kernel(const float* __restrict__ pos) {
    int gw   = (blockIdx.x * blockDim.x + threadIdx.x) >> 5;  // particle
    int lane = threadIdx.x & 31;
    if (gw >= NB * NPTS) return;

    float tx = TWO_PI_L * (pos[gw*3 + 0] - HALF_L);
    float ty = TWO_PI_L * (pos[gw*3 + 1] - HALF_L);
    float tz = TWO_PI_L * (pos[gw*3 + 2] - HALF_L);

    float n = (float)(lane - 15);
    float sy, cy, sz, cz;
    sincosf(n * ty, &sy, &cy);
    sincosf(n * tz, &sz, &cz);
    bool valid = (lane < NM);
    float2 ey = valid ? make_float2(cy, -sy) : make_float2(0.f, 0.f);
    float2 ez = valid ? make_float2(cz, -sz) : make_float2(0.f, 0.f);

    g_Ez2[gw*32 + lane] = ez;
    g_E3[(gw*3 + 1)*32 + lane] = ey;
    g_E3[(gw*3 + 2)*32 + lane] = ez;

    float sx, cx;
    sincosf(tx, &sx, &cx);
    float2 e1x = make_float2(cx, -sx);
    float2 ex  = make_float2(1.f, 0.f);
    float2* row = &g_Exy[gw * (NXH*32)];
#pragma unroll
    for (int it = 0; it < NXH; it++) {
        if (lane == 0) g_E3[(gw*3 + 0)*32 + 15 + it] = ex;  // Ex[nx=it]
        row[it*32 + lane] = cmul(ex, ey);
        ex = cmul(ex, e1x);
    }
}

// ---------------------------------------------------------------------------
// 4) Scatter (FROZEN: 278-280 us across 5 runs). 128-thread CTA per
//    (ixh, b, split); thread tile (2 iy) x (4 z) x (4 ch). Double-buffered
//    cp.async staging.
// ---------------------------------------------------------------------------
__global__ void __launch_bounds__(128, 4) scatter_kernel(const float* __restrict__ charge) {
    const int ixh   = blockIdx.x;        // 0..15
    const int b     = blockIdx.y;
    const int split = blockIdx.z;
    const int tid   = threadIdx.x;
    const int iy0   = (tid >> 3) * 2;    // 0,2,..,30
    const int z0    = (tid & 7) * 4;     // 0,4,..,28
    const int jstart = split * JCHUNK;
    const int jend   = jstart + JCHUNK;

    __shared__ __align__(128) float2 sXY[2][PCHUNK][32];   // raw exy   2x8 KB
    __shared__ __align__(128) float2 sEz[2][PCHUNK][32];   //           2x8 KB
    __shared__ __align__(128) float4 sQ [2][PCHUNK];       //           2x0.5 KB

    auto stage = [&](int cn, int bf) {
        int j0 = jstart + cn * PCHUNK;
        for (int idx = tid; idx < 1056; idx += 128) {
            if (idx < 512) {
                int p = idx >> 4, o = (idx & 15) * 2;
                int j = j0 + p;
                int js = (j < jend) ? j : jstart;
                int sz = (j < jend) ? 16 : 0;
                cp16(smem_u32(&sXY[bf][p][o]),
                     &g_Exy[((b*NPTS + js)*NXH + ixh)*32 + o], sz);
            } else if (idx < 1024) {
                int p = (idx - 512) >> 4, o = ((idx - 512) & 15) * 2;
                int j = j0 + p;
                int js = (j < jend) ? j : jstart;
                int sz = (j < jend) ? 16 : 0;
                cp16(smem_u32(&sEz[bf][p][o]),
                     &g_Ez2[(b*NPTS + js)*32 + o], sz);
            } else {
                int p = idx - 1024;
                int j = j0 + p;
                int js = (j < jend) ? j : jstart;
                int sz = (j < jend) ? 16 : 0;
                cp16(smem_u32(&sQ[bf][p]), &charge[(b*NPTS + js)*NCH], sz);
            }
        }
    };

    u64 acc[2][NCH][4];
#pragma unroll
    for (int t = 0; t < 2; t++)
#pragma unroll
        for (int c = 0; c < NCH; c++)
#pragma unroll
            for (int zl = 0; zl < 4; zl++) acc[t][c][zl] = 0ull;

    stage(0, 0);
    cp_commit();

    for (int nck = 0; nck < NCHUNK; nck++) {
        const int bf = nck & 1;
        if (nck + 1 < NCHUNK) {
            stage(nck + 1, (nck + 1) & 1);
            cp_commit();
            cp_wait<1>();
        } else {
            cp_wait<0>();
        }
        __syncthreads();

#pragma unroll 2
        for (int p = 0; p < PCHUNK; p++) {
            float4 xy   = *reinterpret_cast<const float4*>(&sXY[bf][p][iy0]);
            float4 q    = sQ[bf][p];
            float4 ez01 = *reinterpret_cast<const float4*>(&sEz[bf][p][z0]);
            float4 ez23 = *reinterpret_cast<const float4*>(&sEz[bf][p][z0+2]);
            u64 exqA = pk(xy.x, xy.x), eyqA = pk(-xy.y, xy.y);
            u64 exqB = pk(xy.z, xy.z), eyqB = pk(-xy.w, xy.w);
            u64 q0 = pk(q.x, q.x), q1 = pk(q.y, q.y);
            u64 q2 = pk(q.z, q.z), q3 = pk(q.w, q.w);
            u64 ezv[4]  = { pk(ez01.x, ez01.y), pk(ez01.z, ez01.w),
                            pk(ez23.x, ez23.y), pk(ez23.z, ez23.w) };
            u64 ezvS[4] = { pk(ez01.y, ez01.x), pk(ez01.w, ez01.z),
                            pk(ez23.y, ez23.x), pk(ez23.w, ez23.z) };
#pragma unroll
            for (int zl = 0; zl < 4; zl++) {
                u64 xyzA = ffma2(eyqA, ezvS[zl], fmul2(exqA, ezv[zl]));
                u64 xyzB = ffma2(eyqB, ezvS[zl], fmul2(exqB, ezv[zl]));
                acc[0][0][zl] = ffma2(q0, xyzA, acc[0][0][zl]);
                acc[0][1][zl] = ffma2(q1, xyzA, acc[0][1][zl]);
                acc[0][2][zl] = ffma2(q2, xyzA, acc[0][2][zl]);
                acc[0][3][zl] = ffma2(q3, xyzA, acc[0][3][zl]);
                acc[1][0][zl] = ffma2(q0, xyzB, acc[1][0][zl]);
                acc[1][1][zl] = ffma2(q1, xyzB, acc[1][1][zl]);
                acc[1][2][zl] = ffma2(q2, xyzB, acc[1][2][zl]);
                acc[1][3][zl] = ffma2(q3, xyzB, acc[1][3][zl]);
            }
        }
        __syncthreads();
    }

#pragma unroll
    for (int t = 0; t < 2; t++) {
        int iy = iy0 + t;
        if (iy < NM) {
#pragma unroll
            for (int zl = 0; zl < 4; zl++) {
                int z = z0 + zl;
                if (z < NM) {
#pragma unroll
                    for (int c = 0; c < NCH; c++) {
                        g_Fp[(((split*NB + b)*NCH + c)*NXH + ixh)*NPLANE + iy*NM + z] =
                            upk(acc[t][c][zl]);
                    }
                }
            }
        }
    }
}

// ---------------------------------------------------------------------------
// 4b) Reduce partials + fold mult & Hermitian weight, writing the
//     channel-pair-packed layout:
//       g_FA[q] = { (F0.x,F1.x), (F0.y,F1.y) },  g_FB[q] = channels 2,3
//     q = ((b*NXH+ixh)*32+iy)*32 + z, zero-padded at iy/z = 31.
// ---------------------------------------------------------------------------
__global__ void reduce_kernel() {
    int q = blockIdx.x * blockDim.x + threadIdx.x;
    if (q >= FQN) return;
    int z   = q & 31;
    int iy  = (q >> 5) & 31;
    int ixh = (q >> 10) & 15;
    int b   = q >> 14;
    float2 F[NCH];
#pragma unroll
    for (int c = 0; c < NCH; c++) F[c] = make_float2(0.f, 0.f);
    if (z < NM && iy < NM) {
        const int TOT = NB*NCH*NXH*NPLANE;
        float m = g_mult[(15 + ixh)*NPLANE + iy*NM + z];
        if (ixh > 0) m *= 2.0f;              // Hermitian half-space weight
#pragma unroll
        for (int c = 0; c < NCH; c++) {
            int src = (((b)*NCH + c)*NXH + ixh)*NPLANE + iy*NM + z;
            float2 s = make_float2(0.f, 0.f);
#pragma unroll
            for (int sp = 0; sp < NSPLIT; sp++) {
                float2 v = g_Fp[sp*TOT + src];
                s.x += v.x; s.y += v.y;
            }
            F[c] = make_float2(s.x * m, s.y * m);
        }
    }
    g_FA[q] = make_ulonglong2(pk(F[0].x, F[1].x), pk(F[0].y, F[1].y));
    g_FB[q] = make_ulonglong2(pk(F[2].x, F[3].x), pk(F[2].y, F[3].y));
}

// ---------------------------------------------------------------------------
// 5) Gather: one CTA per (batch, 12 particles). Channel-pair-packed acc
//    (2 u64/particle) frees registers for 12 particles -> F L2 traffic drops
//    1.5 GB -> 1.02 GB. e2 computed in broadcast-component form; the acc
//    pair directly holds (energy_c0, energy_c1) — no horizontal add.
//    Register audit: acc 48 + FrP 32 + working ~36 ≈ 116 < 128 @ (256,2).
// ---------------------------------------------------------------------------
__global__ void __launch_bounds__(256, 2) gather_kernel(const float* __restrict__ charge,
                                                        float* __restrict__ out) {
    const int b   = blockIdx.y;
    const int j0  = blockIdx.x * GP;
    const int tid = threadIdx.x;
    const int iy  = tid >> 3;
    const int z0  = (tid & 7) * 4;       // covers z0..z0+3
    const bool act = (iy < NM);
    const int warp = tid >> 5;
    const int lane = tid & 31;

    __shared__ float2 pEx[GP][NXH];
    __shared__ float2 pEy[GP][32];
    __shared__ u64    pEzX[GP][32];      // (ez.x, ez.x) broadcast, slot 31 zero
    __shared__ u64    pEzY[GP][32];      // (ez.y, ez.y) broadcast
    __shared__ float4 pCh[GP];
    __shared__ float  red[8][GP*4];
    __shared__ float  sfin[GP*4];

    // particle data from g_E3
    for (int idx = tid; idx < GP*32; idx += 256) {
        int p = idx / 32, i = idx & 31;
        int base = (b*NPTS + j0 + p) * 3;
        pEy[p][i] = g_E3[(base + 1)*32 + i];
        float2 vz = g_E3[(base + 2)*32 + i];
        pEzX[p][i] = pk(vz.x, vz.x);
        pEzY[p][i] = pk(vz.y, vz.y);
    }
    if (tid < GP*NXH) {
        int p = tid >> 4, i = tid & 15;
        pEx[p][i] = g_E3[((b*NPTS + j0 + p)*3 + 0)*32 + 15 + i];
    }
    if (tid < GP) {
        pCh[tid] = *reinterpret_cast<const float4*>(&charge[(b*NPTS + j0 + tid)*NCH]);
    }
    __syncthreads();

    u64 accA[GP], accB[GP];              // (c0,c1) and (c2,c3) energy pairs
#pragma unroll
    for (int p = 0; p < GP; p++) { accA[p] = 0ull; accB[p] = 0ull; }

    for (int ixh = 0; ixh < NXH; ixh++) {
        if (act) {
            const int q = ((b*NXH + ixh)*32 + iy)*32 + z0;
            // 8 independent LDG.128: packed F pairs, no repacking needed
            ulonglong2 fa0 = g_FA[q],     fa1 = g_FA[q + 1];
            ulonglong2 fa2 = g_FA[q + 2], fa3 = g_FA[q + 3];
            ulonglong2 fb0 = g_FB[q],     fb1 = g_FB[q + 1];
            ulonglong2 fb2 = g_FB[q + 2], fb3 = g_FB[q + 3];
            u64 FAx[4] = {fa0.x, fa1.x, fa2.x, fa3.x};
            u64 FAy[4] = {fa0.y, fa1.y, fa2.y, fa3.y};
            u64 FBx[4] = {fb0.x, fb1.x, fb2.x, fb3.x};
            u64 FBy[4] = {fb0.y, fb1.y, fb2.y, fb3.y};
#pragma unroll
            for (int p = 0; p < GP; p++) {
                float2 exy = cmul(pEx[p][ixh], pEy[p][iy]);
                u64 exB  = pk(exy.x, exy.x);
                u64 eyBp = pk(exy.y, exy.y);
                u64 eyBn = pk(-exy.y, -exy.y);
#pragma unroll
                for (int zl = 0; zl < 4; zl++) {
                    u64 ezX = pEzX[p][z0 + zl];
                    u64 ezY = pEzY[p][z0 + zl];
                    // e2 = exy*ez in broadcast components
                    u64 e2x = ffma2(eyBn, ezY, fmul2(exB, ezX));
                    u64 e2y = ffma2(eyBp, ezX, fmul2(exB, ezY));
                    accA[p] = ffma2(FAx[zl], e2x, accA[p]);
                    accA[p] = ffma2(FAy[zl], e2y, accA[p]);
                    accB[p] = ffma2(FBx[zl], e2x, accB[p]);
                    accB[p] = ffma2(FBy[zl], e2y, accB[p]);
                }
            }
        }
    }
    __syncthreads();

    // block reduction: each thread holds (c0,c1) and (c2,c3) pairs per particle
#pragma unroll
    for (int p = 0; p < GP; p++) {
        float2 a = upk(accA[p]);
        float2 bb = upk(accB[p]);
        float v0 = a.x, v1 = a.y, v2 = bb.x, v3 = bb.y;
#pragma unroll
        for (int off = 16; off > 0; off >>= 1) {
            v0 += __shfl_xor_sync(0xffffffffu, v0, off);
            v1 += __shfl_xor_sync(0xffffffffu, v1, off);
            v2 += __shfl_xor_sync(0xffffffffu, v2, off);
            v3 += __shfl_xor_sync(0xffffffffu, v3, off);
        }
        if (lane == 0) {
            red[warp][p*4 + 0] = v0;
            red[warp][p*4 + 1] = v1;
            red[warp][p*4 + 2] = v2;
            red[warp][p*4 + 3] = v3;
        }
    }
    __syncthreads();
    if (tid < GP*4) {
        float s = 0.0f;
#pragma unroll
        for (int w = 0; w < 8; w++) s += red[w][tid];
        sfin[tid] = s;
    }
    __syncthreads();
    if (tid < GP) {
        float diag = g_diag;
        float4 c4 = pCh[tid];
        float e = c4.x * (sfin[tid*4 + 0]*INV2V - diag)
                + c4.y * (sfin[tid*4 + 1]*INV2V - diag)
                + c4.z * (sfin[tid*4 + 2]*INV2V - diag)
                + c4.w * (sfin[tid*4 + 3]*INV2V - diag);
        out[b*NPTS + j0 + tid] = e;
    }
}

// ---------------------------------------------------------------------------
// Launch
// ---------------------------------------------------------------------------
extern "C" void kernel_launch(void* const* d_in, const int* in_sizes, int n_in,
                              void* d_out, int out_size) {
    const float* pos    = (const float*)d_in[0];
    const float* charge = (const float*)d_in[1];
    const float* shift  = (const float*)d_in[2];
    const float* amp    = (const float*)d_in[3];
    float* out = (float*)d_out;

    mult_kernel<<<(NK + 255)/256, 256>>>(shift, amp);
    diag_kernel<<<1, 1024>>>();
    etab_kernel<<<(NB*NPTS*32 + 255)/256, 256>>>(pos);
    scatter_kernel<<<dim3(NXH, NB, NSPLIT), 128>>>(charge);
    reduce_kernel<<<(FQN + 255)/256, 256>>>();
    gather_kernel<<<dim3(NPTS/GP, NB), 256>>>(charge, out);
}

// round 16
// speedup vs baseline: 1.2159x; 1.2159x over previous
#include <cuda_runtime.h>
#include <cstdint>

// Problem constants
#define NM      31
#define NPLANE  (NM*NM)        // 961
#define NK      (NM*NM*NM)     // 29791
#define NB      8
#define NPTS    3000
#define NCH     4
#define NBW     12
#define NXH     16             // half-space planes nx = 0..15
#define NSPLIT  4
#define JCHUNK  (NPTS/NSPLIT)  // 750
#define PCHUNK  32             // particles per pipeline stage
#define NCHUNK  ((JCHUNK + PCHUNK - 1)/PCHUNK)   // 24
#define TWO_PI_L 0.628318530717958647692f
#define HALF_L   5.0f
#define INV2V    (1.0f/2000.0f)

typedef unsigned long long u64;

// Padded F tensor: [b][ixh][c][iy:32][z:32], zero-padded at iy=31 / z=31
#define FPAD    (NB*NXH*NCH*32*32)     // 524288 float2 = 4.2 MB

// Scratch (static device globals; allocation-free per harness rules)
__device__ __align__(256) float2 g_Exy[NB*NPTS*NXH*32];  // [pidx][ixh][i], 98.3 MB
__device__ __align__(256) float2 g_Ez2[NB*NPTS*32];      // [pidx][i], 6.1 MB
__device__ __align__(256) float2 g_E3[NB*NPTS*3*32];     // [pidx][dim][i], 18.4 MB
__device__ float2 g_Fp[NSPLIT*NB*NCH*NXH*NPLANE];        // partial structure factors
__device__ float2 g_F2[FPAD];                            // mult(+w)-folded, padded
__device__ float  g_mult[NK];
__device__ float  g_diag;

__device__ __forceinline__ float2 cmul(float2 a, float2 b) {
    return make_float2(a.x*b.x - a.y*b.y, a.x*b.y + a.y*b.x);
}
__device__ __forceinline__ u64 pk(float x, float y) {
    u64 r; asm("mov.b64 %0,{%1,%2};" : "=l"(r) : "f"(x), "f"(y)); return r;
}
__device__ __forceinline__ float2 upk(u64 v) {
    float2 f; asm("mov.b64 {%0,%1},%2;" : "=f"(f.x), "=f"(f.y) : "l"(v)); return f;
}
__device__ __forceinline__ u64 swap64(u64 v) {
    float2 f = upk(v); return pk(f.y, f.x);
}
__device__ __forceinline__ u64 ffma2(u64 a, u64 b, u64 c) {
    u64 d; asm("fma.rn.f32x2 %0,%1,%2,%3;" : "=l"(d) : "l"(a), "l"(b), "l"(c)); return d;
}
__device__ __forceinline__ u64 fmul2(u64 a, u64 b) {
    u64 d; asm("mul.rn.f32x2 %0,%1,%2;" : "=l"(d) : "l"(a), "l"(b)); return d;
}
__device__ __forceinline__ uint32_t smem_u32(const void* p) {
    return static_cast<uint32_t>(__cvta_generic_to_shared(p));
}
__device__ __forceinline__ void cp16(uint32_t dst, const void* src, int srcsz) {
    asm volatile("cp.async.cg.shared.global [%0],[%1],16,%2;"
                 :: "r"(dst), "l"(src), "r"(srcsz));
}
__device__ __forceinline__ void cp_commit() {
    asm volatile("cp.async.commit_group;");
}
template<int N> __device__ __forceinline__ void cp_wait() {
    asm volatile("cp.async.wait_group %0;" :: "n"(N));
}

// ---------------------------------------------------------------------------
// 1) mult(k)
// ---------------------------------------------------------------------------
__global__ void mult_kernel(const float* __restrict__ shift,
                            const float* __restrict__ amp) {
    int i = blockIdx.x * blockDim.x + threadIdx.x;
    if (i >= NK) return;
    int ix = i / NPLANE;
    int r  = i - ix * NPLANE;
    int iy = r / NM;
    int iz = r - iy * NM;
    float kx = TWO_PI_L * (float)(ix - 15);
    float ky = TWO_PI_L * (float)(iy - 15);
    float kz = TWO_PI_L * (float)(iz - 15);
    float k2 = kx*kx + ky*ky + kz*kz;
    float m = 0.0f;
#pragma unroll
    for (int b = 0; b < NBW; b++) {
        m += amp[b] * __expf(-k2 * __expf(2.0f * shift[b]));
    }
    if (k2 == 0.0f) m = 0.0f;
    g_mult[i] = m;
}

// ---------------------------------------------------------------------------
// 2) diag_sum
// ---------------------------------------------------------------------------
__global__ void diag_kernel() {
    __shared__ float sh[1024];
    int tid = threadIdx.x;
    float s = 0.0f;
    for (int i = tid; i < NK; i += 1024) s += g_mult[i];
    sh[tid] = s;
    __syncthreads();
    for (int o = 512; o > 0; o >>= 1) {
        if (tid < o) sh[tid] += sh[tid + o];
        __syncthreads();
    }
    if (tid == 0) g_diag = sh[0] * INV2V;
}

// ---------------------------------------------------------------------------
// 3) E tables: one warp per particle, coalesced 256B row stores.
//    Emits: g_Exy (scatter), g_Ez2 (scatter), g_E3 (gather ex/ey/ez).
// ---------------------------------------------------------------------------
__global__ void etab_kernel(const float* __restrict__ pos) {
    int gw   = (blockIdx.x * blockDim.x + threadIdx.x) >> 5;  // particle
    int lane = threadIdx.x & 31;
    if (gw >= NB * NPTS) return;

    float tx = TWO_PI_L * (pos[gw*3 + 0] - HALF_L);
    float ty = TWO_PI_L * (pos[gw*3 + 1] - HALF_L);
    float tz = TWO_PI_L * (pos[gw*3 + 2] - HALF_L);

    float n = (float)(lane - 15);
    float sy, cy, sz, cz;
    sincosf(n * ty, &sy, &cy);
    sincosf(n * tz, &sz, &cz);
    bool valid = (lane < NM);
    float2 ey = valid ? make_float2(cy, -sy) : make_float2(0.f, 0.f);
    float2 ez = valid ? make_float2(cz, -sz) : make_float2(0.f, 0.f);

    g_Ez2[gw*32 + lane] = ez;
    g_E3[(gw*3 + 1)*32 + lane] = ey;
    g_E3[(gw*3 + 2)*32 + lane] = ez;

    float sx, cx;
    sincosf(tx, &sx, &cx);
    float2 e1x = make_float2(cx, -sx);
    float2 ex  = make_float2(1.f, 0.f);
    float2* row = &g_Exy[gw * (NXH*32)];
#pragma unroll
    for (int it = 0; it < NXH; it++) {
        if (lane == 0) g_E3[(gw*3 + 0)*32 + 15 + it] = ex;  // Ex[nx=it]
        row[it*32 + lane] = cmul(ex, ey);
        ex = cmul(ex, e1x);
    }
}

// ---------------------------------------------------------------------------
// 4) Scatter (FROZEN: 277.6-280 us across 5 runs). 128-thread CTA per
//    (ixh, b, split); thread tile (2 iy) x (4 z) x (4 ch). Double-buffered
//    cp.async staging.
// ---------------------------------------------------------------------------
__global__ void __launch_bounds__(128, 4) scatter_kernel(const float* __restrict__ charge) {
    const int ixh   = blockIdx.x;        // 0..15
    const int b     = blockIdx.y;
    const int split = blockIdx.z;
    const int tid   = threadIdx.x;
    const int iy0   = (tid >> 3) * 2;    // 0,2,..,30
    const int z0    = (tid & 7) * 4;     // 0,4,..,28
    const int jstart = split * JCHUNK;
    const int jend   = jstart + JCHUNK;

    __shared__ __align__(128) float2 sXY[2][PCHUNK][32];   // raw exy   2x8 KB
    __shared__ __align__(128) float2 sEz[2][PCHUNK][32];   //           2x8 KB
    __shared__ __align__(128) float4 sQ [2][PCHUNK];       //           2x0.5 KB

    auto stage = [&](int cn, int bf) {
        int j0 = jstart + cn * PCHUNK;
        for (int idx = tid; idx < 1056; idx += 128) {
            if (idx < 512) {
                int p = idx >> 4, o = (idx & 15) * 2;
                int j = j0 + p;
                int js = (j < jend) ? j : jstart;
                int sz = (j < jend) ? 16 : 0;
                cp16(smem_u32(&sXY[bf][p][o]),
                     &g_Exy[((b*NPTS + js)*NXH + ixh)*32 + o], sz);
            } else if (idx < 1024) {
                int p = (idx - 512) >> 4, o = ((idx - 512) & 15) * 2;
                int j = j0 + p;
                int js = (j < jend) ? j : jstart;
                int sz = (j < jend) ? 16 : 0;
                cp16(smem_u32(&sEz[bf][p][o]),
                     &g_Ez2[(b*NPTS + js)*32 + o], sz);
            } else {
                int p = idx - 1024;
                int j = j0 + p;
                int js = (j < jend) ? j : jstart;
                int sz = (j < jend) ? 16 : 0;
                cp16(smem_u32(&sQ[bf][p]), &charge[(b*NPTS + js)*NCH], sz);
            }
        }
    };

    u64 acc[2][NCH][4];
#pragma unroll
    for (int t = 0; t < 2; t++)
#pragma unroll
        for (int c = 0; c < NCH; c++)
#pragma unroll
            for (int zl = 0; zl < 4; zl++) acc[t][c][zl] = 0ull;

    stage(0, 0);
    cp_commit();

    for (int nck = 0; nck < NCHUNK; nck++) {
        const int bf = nck & 1;
        if (nck + 1 < NCHUNK) {
            stage(nck + 1, (nck + 1) & 1);
            cp_commit();
            cp_wait<1>();
        } else {
            cp_wait<0>();
        }
        __syncthreads();

#pragma unroll 2
        for (int p = 0; p < PCHUNK; p++) {
            float4 xy   = *reinterpret_cast<const float4*>(&sXY[bf][p][iy0]);
            float4 q    = sQ[bf][p];
            float4 ez01 = *reinterpret_cast<const float4*>(&sEz[bf][p][z0]);
            float4 ez23 = *reinterpret_cast<const float4*>(&sEz[bf][p][z0+2]);
            u64 exqA = pk(xy.x, xy.x), eyqA = pk(-xy.y, xy.y);
            u64 exqB = pk(xy.z, xy.z), eyqB = pk(-xy.w, xy.w);
            u64 q0 = pk(q.x, q.x), q1 = pk(q.y, q.y);
            u64 q2 = pk(q.z, q.z), q3 = pk(q.w, q.w);
            u64 ezv[4]  = { pk(ez01.x, ez01.y), pk(ez01.z, ez01.w),
                            pk(ez23.x, ez23.y), pk(ez23.z, ez23.w) };
            u64 ezvS[4] = { pk(ez01.y, ez01.x), pk(ez01.w, ez01.z),
                            pk(ez23.y, ez23.x), pk(ez23.w, ez23.z) };
#pragma unroll
            for (int zl = 0; zl < 4; zl++) {
                u64 xyzA = ffma2(eyqA, ezvS[zl], fmul2(exqA, ezv[zl]));
                u64 xyzB = ffma2(eyqB, ezvS[zl], fmul2(exqB, ezv[zl]));
                acc[0][0][zl] = ffma2(q0, xyzA, acc[0][0][zl]);
                acc[0][1][zl] = ffma2(q1, xyzA, acc[0][1][zl]);
                acc[0][2][zl] = ffma2(q2, xyzA, acc[0][2][zl]);
                acc[0][3][zl] = ffma2(q3, xyzA, acc[0][3][zl]);
                acc[1][0][zl] = ffma2(q0, xyzB, acc[1][0][zl]);
                acc[1][1][zl] = ffma2(q1, xyzB, acc[1][1][zl]);
                acc[1][2][zl] = ffma2(q2, xyzB, acc[1][2][zl]);
                acc[1][3][zl] = ffma2(q3, xyzB, acc[1][3][zl]);
            }
        }
        __syncthreads();
    }

#pragma unroll
    for (int t = 0; t < 2; t++) {
        int iy = iy0 + t;
        if (iy < NM) {
#pragma unroll
            for (int zl = 0; zl < 4; zl++) {
                int z = z0 + zl;
                if (z < NM) {
#pragma unroll
                    for (int c = 0; c < NCH; c++) {
                        g_Fp[(((split*NB + b)*NCH + c)*NXH + ixh)*NPLANE + iy*NM + z] =
                            upk(acc[t][c][zl]);
                    }
                }
            }
        }
    }
}

// ---------------------------------------------------------------------------
// 4b) Reduce partials + fold mult AND Hermitian weight into padded layout
// ---------------------------------------------------------------------------
__global__ void reduce_kernel() {
    int idx = blockIdx.x * blockDim.x + threadIdx.x;
    if (idx >= FPAD) return;
    int z   = idx & 31;
    int iy  = (idx >> 5) & 31;
    int c   = (idx >> 10) & 3;
    int ixh = (idx >> 12) & 15;
    int b   = idx >> 16;
    float2 s = make_float2(0.0f, 0.0f);
    if (z < NM && iy < NM) {
        const int TOT = NB*NCH*NXH*NPLANE;
        int src = (((b)*NCH + c)*NXH + ixh)*NPLANE + iy*NM + z;
#pragma unroll
        for (int sp = 0; sp < NSPLIT; sp++) {
            float2 v = g_Fp[sp*TOT + src];
            s.x += v.x; s.y += v.y;
        }
        float m = g_mult[(15 + ixh)*NPLANE + iy*NM + z];
        if (ixh > 0) m *= 2.0f;              // Hermitian half-space weight
        s.x *= m; s.y *= m;
    }
    g_F2[idx] = s;
}

// ---------------------------------------------------------------------------
// 5) Gather (r14 form, best measured — dur 606.2 total). One CTA per
//    (batch, 8 particles); Fr loaded in-loop via coalesced LDG.128 from the
//    padded L2-resident tensor. No prefetch (r13: −25 us when removed), no
//    smem/register F staging (r11/r12/r15: all regressed).
// ---------------------------------------------------------------------------
__global__ void __launch_bounds__(256, 2) gather_kernel(const float* __restrict__ charge,
                                                        float* __restrict__ out) {
    const int b   = blockIdx.y;
    const int j0  = blockIdx.x * 8;
    const int tid = threadIdx.x;
    const int iy  = tid >> 3;
    const int zh  = (tid & 7) * 2;       // z0 = zh*2
    const bool act = (iy < NM);
    const int warp = tid >> 5;
    const int lane = tid & 31;

    __shared__ float2     pEx[8][NXH];
    __shared__ float2     pEy[8][32];
    __shared__ ulonglong2 pEz[8][16];    // z pairs, slot z=31 zero
    __shared__ float4     pCh[8];
    __shared__ float      red[8][32];
    __shared__ float      sfin[32];

    u64* pEzU = reinterpret_cast<u64*>(pEz);

    // particle data from g_E3
    for (int idx = tid; idx < 8*32; idx += 256) {
        int p = idx >> 5, i = idx & 31;
        int base = (b*NPTS + j0 + p) * 3;
        pEy[p][i] = g_E3[(base + 1)*32 + i];
        float2 vz = g_E3[(base + 2)*32 + i];
        pEzU[p*32 + i] = pk(vz.x, vz.y);
    }
    if (tid < 8*NXH) {
        int p = tid >> 4, i = tid & 15;
        pEx[p][i] = g_E3[((b*NPTS + j0 + p)*3 + 0)*32 + 15 + i];
    }
    if (tid < 8) {
        pCh[tid] = *reinterpret_cast<const float4*>(&charge[(b*NPTS + j0 + tid)*NCH]);
    }
    __syncthreads();

    u64 acc[8][NCH];
#pragma unroll
    for (int p = 0; p < 8; p++)
#pragma unroll
        for (int c = 0; c < NCH; c++) acc[p][c] = 0ull;

    const ulonglong2* Fbase = reinterpret_cast<const ulonglong2*>(g_F2);

    for (int ixh = 0; ixh < NXH; ixh++) {
        if (act) {
            u64 Fr[NCH][4];
#pragma unroll
            for (int c = 0; c < NCH; c++) {
                const ulonglong2* fp =
                    Fbase + (((b*NXH + ixh)*NCH + c)*32 + iy)*16 + zh;
                ulonglong2 f0 = fp[0];
                ulonglong2 f1 = fp[1];
                Fr[c][0] = f0.x; Fr[c][1] = f0.y;
                Fr[c][2] = f1.x; Fr[c][3] = f1.y;
            }
#pragma unroll
            for (int p = 0; p < 8; p++) {
                float2 exy = cmul(pEx[p][ixh], pEy[p][iy]);
                u64 exq = pk(exy.x, exy.x);
                u64 eyq = pk(-exy.y, exy.y);
                ulonglong2 ez01 = pEz[p][zh];
                ulonglong2 ez23 = pEz[p][zh + 1];
                u64 ezv[4] = {ez01.x, ez01.y, ez23.x, ez23.y};
#pragma unroll
                for (int zl = 0; zl < 4; zl++) {
                    u64 ez = ezv[zl];
                    u64 e2 = ffma2(eyq, swap64(ez), fmul2(exq, ez));   // exy*ez
                    acc[p][0] = ffma2(e2, Fr[0][zl], acc[p][0]);
                    acc[p][1] = ffma2(e2, Fr[1][zl], acc[p][1]);
                    acc[p][2] = ffma2(e2, Fr[2][zl], acc[p][2]);
                    acc[p][3] = ffma2(e2, Fr[3][zl], acc[p][3]);
                }
            }
        }
    }
    __syncthreads();

    // horizontal add (Re part) then block reduction
#pragma unroll
    for (int p = 0; p < 8; p++) {
#pragma unroll
        for (int c = 0; c < NCH; c++) {
            float2 f = upk(acc[p][c]);
            float v = f.x + f.y;
#pragma unroll
            for (int off = 16; off > 0; off >>= 1)
                v += __shfl_xor_sync(0xffffffffu, v, off);
            if (lane == 0) red[warp][p*NCH + c] = v;
        }
    }
    __syncthreads();
    if (tid < 32) {
        float s = 0.0f;
#pragma unroll
        for (int w = 0; w < 8; w++) s += red[w][tid];
        sfin[tid] = s;
    }
    __syncthreads();
    if (tid < 8) {
        float diag = g_diag;
        float4 c4 = pCh[tid];
        float e = c4.x * (sfin[tid*NCH + 0]*INV2V - diag)
                + c4.y * (sfin[tid*NCH + 1]*INV2V - diag)
                + c4.z * (sfin[tid*NCH + 2]*INV2V - diag)
                + c4.w * (sfin[tid*NCH + 3]*INV2V - diag);
        out[b*NPTS + j0 + tid] = e;
    }
}

// ---------------------------------------------------------------------------
// Launch
// ---------------------------------------------------------------------------
extern "C" void kernel_launch(void* const* d_in, const int* in_sizes, int n_in,
                              void* d_out, int out_size) {
    const float* pos    = (const float*)d_in[0];
    const float* charge = (const float*)d_in[1];
    const float* shift  = (const float*)d_in[2];
    const float* amp    = (const float*)d_in[3];
    float* out = (float*)d_out;

    mult_kernel<<<(NK + 255)/256, 256>>>(shift, amp);
    diag_kernel<<<1, 1024>>>();
    etab_kernel<<<(NB*NPTS*32 + 255)/256, 256>>>(pos);
    scatter_kernel<<<dim3(NXH, NB, NSPLIT), 128>>>(charge);
    reduce_kernel<<<(FPAD + 255)/256, 256>>>();
    gather_kernel<<<dim3(NPTS/8, NB), 256>>>(charge, out);
}